// round 14
// baseline (speedup 1.0000x reference)
#include <cuda_runtime.h>
#include <cuda_fp16.h>

#define D 128
#define MAXN 40000
#define MAXE 640000

// ---------------- scratch (static device globals; no allocation) -------------
__device__ float g_deg[MAXN];
__device__ int   g_cnt[MAXN];
__device__ int   g_offs[MAXN + 1];
__device__ int   g_cursor[MAXN];
__device__ __align__(16) int2   g_edge[MAXE];      // {src, nrm bits}
__device__ __align__(16) __half g_Hh[MAXN * D];    // h = A @ W, fp16 (gathered)
__device__ __align__(16) float  g_G[MAXN * D];     // post-agg activations (fp32)
__device__ int   g_is64;                           // edge_index dtype flag

// ---------------- tf32 helpers -------------------------------------------------
__device__ __forceinline__ unsigned f2tf32(float x) {
    unsigned r;
    asm("cvt.rna.tf32.f32 %0, %1;" : "=r"(r) : "f"(x));
    return r;
}
__device__ __forceinline__ void mma_tf32(float* c, const unsigned* a,
                                         unsigned b0, unsigned b1) {
    asm volatile(
        "mma.sync.aligned.m16n8k8.row.col.f32.tf32.tf32.f32 "
        "{%0,%1,%2,%3}, {%4,%5,%6,%7}, {%8,%9}, {%0,%1,%2,%3};\n"
        : "+f"(c[0]), "+f"(c[1]), "+f"(c[2]), "+f"(c[3])
        : "r"(a[0]), "r"(a[1]), "r"(a[2]), "r"(a[3]), "r"(b0), "r"(b1));
}

// ---------------- init + dtype probe (R8 proven) -------------------------------
__global__ void k_init(const void* __restrict__ ei, int n) {
    int i = blockIdx.x * blockDim.x + threadIdx.x;
    if (i < n) { g_deg[i] = 1.0f; g_cnt[i] = 0; }   // 1.0 = self-loop weight
    if (blockIdx.x == 0) {
        const long long* p = (const long long*)ei;
        bool bad = false;
        for (int j = threadIdx.x; j < 1024; j += blockDim.x) {
            long long v = p[j];
            if (v < 0 || v >= MAXN) bad = true;
        }
        bad = __syncthreads_or(bad);
        if (threadIdx.x == 0) g_is64 = bad ? 0 : 1;
    }
}

__device__ __forceinline__ int edge_at(const void* ei, long long idx) {
    if (g_is64) return (int)((const long long*)ei)[idx];
    return ((const int*)ei)[idx];
}

// 4 independent edges per thread (coalesced stride-256 batches) -> MLP 4.
__global__ void k_deg(const void* __restrict__ ei,
                      const float* __restrict__ ea, int e) {
    int base = blockIdx.x * 1024 + threadIdx.x;
    int   dsts[4];
    float w[4];
    bool  ok[4];
#pragma unroll
    for (int j = 0; j < 4; j++) {
        int i = base + j * 256;
        ok[j] = i < e;
        if (ok[j]) {
            dsts[j] = edge_at(ei, (long long)e + i);
            w[j] = ea[i];
        }
    }
#pragma unroll
    for (int j = 0; j < 4; j++) {
        if (ok[j]) {
            atomicAdd(&g_deg[dsts[j]], w[j]);
            atomicAdd(&g_cnt[dsts[j]], 1);
        }
    }
}

// Single-block exclusive scan of g_cnt -> g_offs / g_cursor (n <= 40960)
__global__ void k_scan(int n) {
    __shared__ int s[1024];
    int t = threadIdx.x;
    int ch = (n + 1023) >> 10;
    int base = t * ch;
    int sum = 0;
    for (int j = 0; j < ch; j++) {
        int idx = base + j;
        if (idx < n) sum += g_cnt[idx];
    }
    s[t] = sum;
    __syncthreads();
    for (int off = 1; off < 1024; off <<= 1) {
        int v = (t >= off) ? s[t - off] : 0;
        __syncthreads();
        s[t] += v;
        __syncthreads();
    }
    if (t == 1023) g_offs[n] = s[1023];
    int prefix = (t == 0) ? 0 : s[t - 1];
    for (int j = 0; j < ch; j++) {
        int idx = base + j;
        if (idx < n) {
            g_offs[idx]   = prefix;
            g_cursor[idx] = prefix;
            prefix += g_cnt[idx];
        }
    }
}

// 4 independent atomic->store chains per thread.
__global__ void k_fill(const void* __restrict__ ei,
                       const float* __restrict__ ea, int e) {
    int base = blockIdx.x * 1024 + threadIdx.x;
#pragma unroll
    for (int j = 0; j < 4; j++) {
        int i = base + j * 256;
        if (i < e) {
            int src = edge_at(ei, i);
            int dst = edge_at(ei, (long long)e + i);
            float nrm = rsqrtf(g_deg[src]) * ea[i] * rsqrtf(g_deg[dst]);
            int pos = atomicAdd(&g_cursor[dst], 1);
            g_edge[pos] = make_int2(src, __float_as_int(nrm));
        }
    }
}

// ---------------- tf32 tensor-core GEMM (R13 proven, fp16 epilogue) ----------
template <int USE_G>
__global__ void __launch_bounds__(256) k_gemm(const float* __restrict__ Ain,
                                              const float* __restrict__ W,
                                              int nrows) {
    const float* __restrict__ A = USE_G ? (const float*)g_G : Ain;
    extern __shared__ unsigned wf[];   // [ks16][nf16][lane32][2] tf32

    int tid = threadIdx.x;
    for (int s = tid; s < 16 * 16 * 32; s += 256) {
        int lane = s & 31;
        int nf = (s >> 5) & 15;
        int ks = s >> 9;
        int k = ks * 8 + (lane & 3);
        int nn = nf * 8 + (lane >> 2);
        unsigned lo = f2tf32(W[k * D + nn]);
        unsigned hi = f2tf32(W[(k + 4) * D + nn]);
        *(uint2*)&wf[s * 2] = make_uint2(lo, hi);
    }
    __syncthreads();

    int wid = tid >> 5, lane = tid & 31;
    int ly = lane >> 2, lx = lane & 3;
    int rowbase = blockIdx.x * 128 + wid * 16;
    int ra = rowbase + ly;     if (ra >= nrows) ra = nrows - 1;
    int rb = rowbase + ly + 8; if (rb >= nrows) rb = nrows - 1;
    const float* pa = A + (size_t)ra * D + lx;
    const float* pb = A + (size_t)rb * D + lx;

    float acc[16][4];
#pragma unroll
    for (int nf = 0; nf < 16; nf++)
#pragma unroll
        for (int j = 0; j < 4; j++) acc[nf][j] = 0.0f;

    unsigned a_cur[4], a_nxt[4];
    a_cur[0] = f2tf32(pa[0]); a_cur[1] = f2tf32(pb[0]);
    a_cur[2] = f2tf32(pa[4]); a_cur[3] = f2tf32(pb[4]);

#pragma unroll
    for (int ks = 0; ks < 16; ks++) {
        if (ks < 15) {
            int k0 = (ks + 1) * 8;
            a_nxt[0] = f2tf32(pa[k0]);     a_nxt[1] = f2tf32(pb[k0]);
            a_nxt[2] = f2tf32(pa[k0 + 4]); a_nxt[3] = f2tf32(pb[k0 + 4]);
        }
        const unsigned* wrow = &wf[(ks * 16 * 32 + lane) * 2];
#pragma unroll
        for (int nf = 0; nf < 16; nf++) {
            uint2 b = *(const uint2*)&wrow[nf * 64];
            mma_tf32(acc[nf], a_cur, b.x, b.y);
        }
#pragma unroll
        for (int j = 0; j < 4; j++) a_cur[j] = a_nxt[j];
    }

    int r1 = rowbase + ly;
    int r2 = rowbase + ly + 8;
#pragma unroll
    for (int nf = 0; nf < 16; nf++) {
        int c = nf * 8 + lx * 2;
        if (r1 < nrows)
            *(__half2*)&g_Hh[(size_t)r1 * D + c] = __floats2half2_rn(acc[nf][0], acc[nf][1]);
        if (r2 < nrows)
            *(__half2*)&g_Hh[(size_t)r2 * D + c] = __floats2half2_rn(acc[nf][2], acc[nf][3]);
    }
}

// ---------------- aggregation: warp/node, half-warp edge split, LDG.128 ------
// lane = half*16 + fid. fid owns 8 features (one uint4 of fp16). Half h
// processes edges ib+h, ib+h+2, ... After the loop, shfl_xor(16) combines the
// two halves -> every lane holds full sums for its feature block.
__device__ __forceinline__ void fma8(float* acc, uint4 v, float wgt) {
    float2 p0 = __half22float2(*(__half2*)&v.x);
    float2 p1 = __half22float2(*(__half2*)&v.y);
    float2 p2 = __half22float2(*(__half2*)&v.z);
    float2 p3 = __half22float2(*(__half2*)&v.w);
    acc[0] += p0.x * wgt; acc[1] += p0.y * wgt;
    acc[2] += p1.x * wgt; acc[3] += p1.y * wgt;
    acc[4] += p2.x * wgt; acc[5] += p2.y * wgt;
    acc[6] += p3.x * wgt; acc[7] += p3.y * wgt;
}

template <int LN>
__global__ void k_agg(const float* __restrict__ bias,
                      const float* __restrict__ gamma, const float* __restrict__ beta,
                      float* __restrict__ outp, int n) {
    int w = (blockIdx.x * blockDim.x + threadIdx.x) >> 5;
    int lane = threadIdx.x & 31;
    if (w >= n) return;
    int half = lane >> 4;
    int fid  = lane & 15;

    const uint4* __restrict__ Hh = (const uint4*)g_Hh;   // 16 uint4 per row

    float acc[8];
#pragma unroll
    for (int j = 0; j < 8; j++) acc[j] = 0.0f;

    if (half == 0) {                       // self-loop: counted once
        float di = rsqrtf(g_deg[w]);
        uint4 v = __ldg(&Hh[(size_t)w * 16 + fid]);
        fma8(acc, v, di * di);
    }

    int ib = g_offs[w];
    int ie = g_offs[w + 1];
    int i = ib + half;
    for (; i + 6 < ie; i += 8) {           // 4 edges per half per batch
        int2 e0 = g_edge[i],     e1 = g_edge[i + 2];
        int2 e2 = g_edge[i + 4], e3 = g_edge[i + 6];
        uint4 v0 = __ldg(&Hh[(size_t)e0.x * 16 + fid]);
        uint4 v1 = __ldg(&Hh[(size_t)e1.x * 16 + fid]);
        uint4 v2 = __ldg(&Hh[(size_t)e2.x * 16 + fid]);
        uint4 v3 = __ldg(&Hh[(size_t)e3.x * 16 + fid]);
        fma8(acc, v0, __int_as_float(e0.y));
        fma8(acc, v1, __int_as_float(e1.y));
        fma8(acc, v2, __int_as_float(e2.y));
        fma8(acc, v3, __int_as_float(e3.y));
    }
    for (; i < ie; i += 2) {
        int2 ed = g_edge[i];
        uint4 v = __ldg(&Hh[(size_t)ed.x * 16 + fid]);
        fma8(acc, v, __int_as_float(ed.y));
    }

    // combine halves: every lane now holds the full 8-feature sums
#pragma unroll
    for (int j = 0; j < 8; j++)
        acc[j] += __shfl_xor_sync(0xffffffffu, acc[j], 16);

    // bias + relu
    float4 ba = ((const float4*)bias)[fid * 2];
    float4 bb = ((const float4*)bias)[fid * 2 + 1];
    acc[0] = fmaxf(acc[0] + ba.x, 0.0f); acc[1] = fmaxf(acc[1] + ba.y, 0.0f);
    acc[2] = fmaxf(acc[2] + ba.z, 0.0f); acc[3] = fmaxf(acc[3] + ba.w, 0.0f);
    acc[4] = fmaxf(acc[4] + bb.x, 0.0f); acc[5] = fmaxf(acc[5] + bb.y, 0.0f);
    acc[6] = fmaxf(acc[6] + bb.z, 0.0f); acc[7] = fmaxf(acc[7] + bb.w, 0.0f);

    if (LN) {
        float s1 = acc[0] + acc[1] + acc[2] + acc[3]
                 + acc[4] + acc[5] + acc[6] + acc[7];
#pragma unroll
        for (int o = 8; o > 0; o >>= 1)        // reduce over 16 fids (halves dup)
            s1 += __shfl_xor_sync(0xffffffffu, s1, o);
        float mu = s1 * (1.0f / 128.0f);
        float d[8], s2 = 0.0f;
#pragma unroll
        for (int j = 0; j < 8; j++) { d[j] = acc[j] - mu; s2 += d[j] * d[j]; }
#pragma unroll
        for (int o = 8; o > 0; o >>= 1)
            s2 += __shfl_xor_sync(0xffffffffu, s2, o);
        float r = rsqrtf(s2 * (1.0f / 128.0f) + 1e-5f);
        float4 ga = ((const float4*)gamma)[fid * 2];
        float4 gb = ((const float4*)gamma)[fid * 2 + 1];
        float4 ea4 = ((const float4*)beta)[fid * 2];
        float4 eb4 = ((const float4*)beta)[fid * 2 + 1];
        acc[0] = d[0] * r * ga.x + ea4.x; acc[1] = d[1] * r * ga.y + ea4.y;
        acc[2] = d[2] * r * ga.z + ea4.z; acc[3] = d[3] * r * ga.w + ea4.w;
        acc[4] = d[4] * r * gb.x + eb4.x; acc[5] = d[5] * r * gb.y + eb4.y;
        acc[6] = d[6] * r * gb.z + eb4.z; acc[7] = d[7] * r * gb.w + eb4.w;
        int h4 = half * 4;
        *(float4*)&outp[(size_t)w * D + fid * 8 + h4] =
            make_float4(acc[h4], acc[h4 + 1], acc[h4 + 2], acc[h4 + 3]);
    } else {
        int h4 = half * 4;
        *(float4*)&g_G[(size_t)w * D + fid * 8 + h4] =
            make_float4(acc[h4], acc[h4 + 1], acc[h4 + 2], acc[h4 + 3]);
    }
}

// ---------------- launch ------------------------------------------------------
extern "C" void kernel_launch(void* const* d_in, const int* in_sizes, int n_in,
                              void* d_out, int out_size) {
    const float* x   = (const float*)d_in[0];
    const void*  ei  = d_in[1];
    const float* ea  = (const float*)d_in[2];
    const float* W1  = (const float*)d_in[3];
    const float* b1  = (const float*)d_in[4];
    const float* W2  = (const float*)d_in[5];
    const float* b2  = (const float*)d_in[6];
    const float* lng = (const float*)d_in[7];
    const float* lnb = (const float*)d_in[8];

    int n = in_sizes[0] / D;   // 40000
    int e = in_sizes[2];       // 640000

    int nb  = (n + 255) / 256;
    int eb4 = (e + 1023) / 1024;

    const int WF_BYTES = 16 * 16 * 32 * 2 * 4;   // 64 KB dynamic smem
    cudaFuncSetAttribute(k_gemm<0>, cudaFuncAttributeMaxDynamicSharedMemorySize, WF_BYTES);
    cudaFuncSetAttribute(k_gemm<1>, cudaFuncAttributeMaxDynamicSharedMemorySize, WF_BYTES);

    k_init<<<nb, 256>>>(ei, n);
    k_deg<<<eb4, 256>>>(ei, ea, e);
    k_scan<<<1, 1024>>>(n);
    k_fill<<<eb4, 256>>>(ei, ea, e);

    int gemm_blocks = (n + 127) / 128;
    int agg_blocks  = (n * 32 + 255) / 256;

    k_gemm<0><<<gemm_blocks, 256, WF_BYTES>>>(x, W1, n);
    k_agg<0><<<agg_blocks, 256>>>(b1, nullptr, nullptr, nullptr, n);
    k_gemm<1><<<gemm_blocks, 256, WF_BYTES>>>(nullptr, W2, n);
    k_agg<1><<<agg_blocks, 256>>>(b2, lng, lnb, (float*)d_out, n);
}